// round 5
// baseline (speedup 1.0000x reference)
#include <cuda_runtime.h>
#include <cuda_fp16.h>

#define V 4096
#define T 4096
#define FW 5
#define BATCH 64
#define SLEN 512
#define NROWS (BATCH * SLEN)   // 32768
#define CDIM (V * FW)          // 20480
#define NT 2                   // t-chunks
#define TT (T / NT)            // 2048 t per chunk
#define MARGIN 4e-4f
#define MAXC 8                 // candidates per (row, chunk)

// fp16 transposed weights Wt[k][v][t]
__device__ __half g_Wt[(size_t)FW * V * T];
// Per-(chunk,row) streaming-softmax state
__device__ float g_m[NT][NROWS];
__device__ float g_S0[NT][NROWS];
__device__ float g_S1[NT][NROWS];
__device__ int   g_cnt[NT][NROWS];
__device__ int   g_cand[NT][NROWS][MAXC];
// Per-row entropy contributions
__device__ float g_rowent[NROWS];

// ---------------------------------------------------------------------------
// Kernel 1: transpose+convert W[t][v][k] (f32) -> Wt[k][v][t] (f16)
// 64-wide t tiles, half2 stores => 128B-coalesced writes.
// grid (CDIM/32, T/64), block (32,8).  Pad 66 (EVEN) so float2 smem reads
// at &tile[c][2*tx] are 8B-aligned for every c.
// ---------------------------------------------------------------------------
__global__ __launch_bounds__(256) void transpose_k(const float* __restrict__ W) {
    __shared__ float tile[32][66];     // [c][t]
    int c0 = blockIdx.x << 5;
    int t0 = blockIdx.y << 6;
    int tx = threadIdx.x;   // 0..31
    int ty = threadIdx.y;   // 0..7

#pragma unroll
    for (int j = 0; j < 8; j++) {
        int r = j * 8 + ty;            // t offset 0..63
        tile[tx][r] = W[(size_t)(t0 + r) * CDIM + c0 + tx];
    }
    __syncthreads();
#pragma unroll
    for (int j = 0; j < 4; j++) {
        int c = j * 8 + ty;            // 0..31
        int cc = c0 + c;
        int v = cc / 5;
        int k = cc - 5 * v;
        float2 f = *(const float2*)&tile[c][2 * tx];
        *(__half2*)(g_Wt + ((size_t)k * V + v) * T + t0 + 2 * tx) =
            __floats2half2_rn(f.x, f.y);
    }
}

// ---------------------------------------------------------------------------
// Kernel 2 (x NT sequential launches): one block per row, one t-chunk.
// Chunk weight slice = 84 MB -> L2 resident across the whole launch.
// Emits chunk-local (m, S0, S1 rel m) + candidates (l >= m_c - MARGIN).
// ---------------------------------------------------------------------------
__global__ __launch_bounds__(256) void gather_chunk_k(const float* __restrict__ bias,
                                                      const int* __restrict__ sent,
                                                      int ct) {
    int row = blockIdx.x;
    int bb = row >> 9;
    int s = row & 511;
    int tid = threadIdx.x;
    int tbase = ct * TT + tid * 8;

    __shared__ float sv[256];
    __shared__ float ss[256];
    __shared__ int scand[MAXC];
    __shared__ int scnt;

    float acc[8];
    {
        const float4* b4 = (const float4*)(bias + tbase);
        float4 b0 = b4[0], b1 = b4[1];
        acc[0] = b0.x; acc[1] = b0.y; acc[2] = b0.z; acc[3] = b0.w;
        acc[4] = b1.x; acc[5] = b1.y; acc[6] = b1.z; acc[7] = b1.w;
    }

#pragma unroll
    for (int k = 0; k < FW; k++) {
        int p = s + k - 2;
        if (p >= 0 && p < SLEN) {
            int tok = __ldg(&sent[(bb << 9) + p]);
            uint4 h = *(const uint4*)(g_Wt + ((size_t)k * V + tok) * T + tbase);
            const __half2* h2 = (const __half2*)&h;
#pragma unroll
            for (int q = 0; q < 4; q++) {
                float2 f = __half22float2(h2[q]);
                acc[q * 2 + 0] += f.x;
                acc[q * 2 + 1] += f.y;
            }
        }
    }

    // ---- chunk max
    float vmax = acc[0];
#pragma unroll
    for (int i = 1; i < 8; i++) vmax = fmaxf(vmax, acc[i]);
    sv[tid] = vmax;
    if (tid == 0) scnt = 0;
    __syncthreads();
#pragma unroll
    for (int off = 128; off > 0; off >>= 1) {
        if (tid < off) sv[tid] = fmaxf(sv[tid], sv[tid + off]);
        __syncthreads();
    }
    float mc = sv[0];
    __syncthreads();

    // ---- S0, S1 (rel mc) + candidates
    float s0 = 0.f, s1 = 0.f;
    float thr = mc - MARGIN;
#pragma unroll
    for (int j = 0; j < 8; j++) {
        float d = acc[j] - mc;
        float e = expf(d);
        s0 += e;
        s1 += d * e;
        if (acc[j] >= thr) {
            int idx = atomicAdd(&scnt, 1);
            if (idx < MAXC) scand[idx] = tbase + j;
        }
    }
    sv[tid] = s0; ss[tid] = s1;
    __syncthreads();
#pragma unroll
    for (int off = 128; off > 0; off >>= 1) {
        if (tid < off) { sv[tid] += sv[tid + off]; ss[tid] += ss[tid + off]; }
        __syncthreads();
    }

    if (tid < MAXC) g_cand[ct][row][tid] = (tid < scnt) ? scand[tid] : 0;
    if (tid == 0) {
        g_m[ct][row]  = mc;
        g_S0[ct][row] = sv[0];
        g_S1[ct][row] = ss[0];
        g_cnt[ct][row] = scnt < MAXC ? scnt : MAXC;
    }
}

// ---------------------------------------------------------------------------
// Kernel 3: per-row combine. Merge chunk states, exact fp32 recheck of
// candidates against original W, emit new_seq / log_prob / row entropy.
// ---------------------------------------------------------------------------
__global__ __launch_bounds__(256) void combine_k(const float* __restrict__ bias,
                                                 const int* __restrict__ sent,
                                                 const float* __restrict__ W,
                                                 float* __restrict__ out) {
    int row = blockIdx.x * 256 + threadIdx.x;
    if (row >= NROWS) return;
    int bb = row >> 9;
    int s = row & 511;

    // merge chunk softmax states
    float m0 = g_m[0][row], m1 = g_m[1][row];
    float mprime = fmaxf(m0, m1);
    float S0 = 0.f, S1 = 0.f;
#pragma unroll
    for (int ct = 0; ct < NT; ct++) {
        float mc = g_m[ct][row];
        float ef = expf(mc - mprime);
        float a = g_S0[ct][row], b = g_S1[ct][row];
        S0 += a * ef;
        S1 += (b + (mc - mprime) * a) * ef;
    }
    float c0 = logf(S0);

    // token cache for exact recheck
    int toks[FW];
#pragma unroll
    for (int k = 0; k < FW; k++) {
        int p = s + k - 2;
        toks[k] = (p >= 0 && p < SLEN) ? __ldg(&sent[(bb << 9) + p]) : -1;
    }

    // exact fp32 logits for all candidates (reference summation order)
    float lex[NT * MAXC];
    int   tex[NT * MAXC];
    int nc = 0;
    float m = -1e30f;
#pragma unroll
    for (int ct = 0; ct < NT; ct++) {
        int n = g_cnt[ct][row];
        for (int i = 0; i < n; i++) {
            int t = g_cand[ct][row][i];
            float l = __ldg(&bias[t]);
#pragma unroll
            for (int k = 0; k < FW; k++)
                if (toks[k] >= 0)
                    l += __ldg(&W[(size_t)t * CDIM + toks[k] * 5 + k]);
            lex[nc] = l; tex[nc] = t; nc++;
            m = fmaxf(m, l);
        }
    }

    float cc = c0 + (mprime - m);   // c consistent with exact m
    float bestlp = -1e30f;
    int bestt = 0x7fffffff;
    for (int i = 0; i < nc; i++) {
        float d = lex[i] - m;       // fp32, matches reference 'shifted'
        float lp = d - cc;          // fp32 quantization -> reference ties
        if (lp > bestlp || (lp == bestlp && tex[i] < bestt)) {
            bestlp = lp; bestt = tex[i];
        }
    }

    out[row] = (float)bestt;
    out[NROWS + row] = bestlp;
    g_rowent[row] = c0 - S1 / S0;
}

// ---------------------------------------------------------------------------
// Kernel 4: deterministic entropy reduction
// ---------------------------------------------------------------------------
__global__ __launch_bounds__(256) void finalize_k(float* __restrict__ out) {
    __shared__ double sd[256];
    int tid = threadIdx.x;
    double a = 0.0;
    for (int i = tid; i < NROWS; i += 256) a += (double)g_rowent[i];
    sd[tid] = a;
    __syncthreads();
#pragma unroll
    for (int off = 128; off > 0; off >>= 1) {
        if (tid < off) sd[tid] += sd[tid + off];
        __syncthreads();
    }
    if (tid == 0)
        out[2 * NROWS] = (float)(sd[0] / ((double)NROWS * (double)T));
}

// ---------------------------------------------------------------------------
extern "C" void kernel_launch(void* const* d_in, const int* in_sizes, int n_in,
                              void* d_out, int out_size) {
    const float* W    = (const float*)d_in[0];   // (T, V, FW) f32
    const float* bias = (const float*)d_in[1];   // (T,) f32
    const int*   sent = (const int*)d_in[2];     // (B, S) int32
    float* out = (float*)d_out;                  // [newseq | logp | entropy]

    dim3 tb(32, 8);
    dim3 tg(CDIM / 32, T / 64);
    transpose_k<<<tg, tb>>>(W);
    for (int ct = 0; ct < NT; ct++)
        gather_chunk_k<<<NROWS, 256>>>(bias, sent, ct);
    combine_k<<<(NROWS + 255) / 256, 256>>>(bias, sent, W, out);
    finalize_k<<<1, 256>>>(out);
}